// round 9
// baseline (speedup 1.0000x reference)
#include <cuda_runtime.h>
#include <cuda_bf16.h>
#include <math.h>

#define B   64
#define NT  20000
#define NT1 20001
#define NTP 20128            // padded dec-partial row stride (74*272, 16B aligned)
#define H4  1024
#define HD  256
#define Y_SZ    (B*NT1)
#define ENC_OFF Y_SZ
#define DEC_OFF (Y_SZ + B*HD)

// k4 sparse GEMM config
#define NCHUNK 1250          // 16-row chunks over 20000 tags
#define RCY  50              // y-blocks
#define CPB  25              // chunks per y-block
#define G4   16              // rows per chunk

// ---------------- scratch (device globals; no allocations) -----------------
__device__ float  g_counts[NT*B];                // [tag][batch]
__device__ int    g_istat[128];                  // [0:64) sum, [64:128) sumsq
__device__ float  g_mu[B], g_rstd[B];
__device__ float  g_accum[B*H4];                 // k4 atomic accumulator (L2-resident)
__device__ float  g_asgw[H4], g_asbw[H4];        // column-sum accumulators
__device__ float2 g_ent[NCHUNK*64*16];           // compacted entries (value=c*g, row)
__device__ int    g_ecnt[NCHUNK*64];             // entries per list
__device__ float  g_pacc[4*B*NTP];               // decoder split-K partials
__device__ float  g_h2[B*H4], g_h3[B*H4], g_encb[B*HD], g_dd[B*H4];
__device__ float  g_pbuf[32*B*H4];               // small-GEMM split-K partials

__device__ __forceinline__ float gelu_exact(float x){
    return 0.5f * x * (1.0f + erff(x * 0.70710678118654752f));
}
__device__ __forceinline__ void cpa16(void* d, const void* s){
    unsigned a = (unsigned)__cvta_generic_to_shared(d);
    asm volatile("cp.async.ca.shared.global [%0], [%1], 16;" :: "r"(a), "l"(s));
}
__device__ __forceinline__ void cpa4(void* d, const void* s){
    unsigned a = (unsigned)__cvta_generic_to_shared(d);
    asm volatile("cp.async.ca.shared.global [%0], [%1], 4;" :: "r"(a), "l"(s));
}
#define CP_COMMIT() asm volatile("cp.async.commit_group;" ::: "memory")
#define CP_WAIT0()  asm volatile("cp.async.wait_group 0;" ::: "memory")
#define FMA2(a,x,y) asm("fma.rn.f32x2 %0, %1, %2, %0;" : "+l"(a) : "l"(x), "l"(y))
#define PACK2(o,f)  asm("mov.b64 %0, {%1,%1};" : "=l"(o) : "f"(f))
#define UNPK(l,h,a) asm("mov.b64 {%0,%1}, %2;" : "=f"(l), "=f"(h) : "l"(a))

// ---------------- K1: scatter multi-hot counts + zero accumulators ----------
__global__ void k1_scatter(const int* __restrict__ tags){
    int p = blockIdx.x*256 + threadIdx.x;       // (b,f) pair, 8192 total
    if (blockIdx.x == 0 && threadIdx.x < 128) g_istat[threadIdx.x] = 0;
    for (int z = p; z < B*H4; z += 8192) g_accum[z] = 0.0f;
    if (p < H4){ g_asgw[p] = 0.0f; g_asbw[p] = 0.0f; }
    int b = p >> 7;
    const int* t = tags + p*16;
    int v[16];
    #pragma unroll
    for (int i = 0; i < 16; i++) v[i] = t[i];
    #pragma unroll
    for (int i = 0; i < 16; i++){
        bool dup = false;
        #pragma unroll
        for (int s = 0; s < 16; s++) if (s < i) dup = dup || (v[s] == v[i]);
        if (!dup) atomicAdd(&g_counts[v[i]*B + b], 1.0f);
    }
}

// ---------------- K2: build compact entry lists + per-batch stats -----------
// thread t = (chunk, b); scans 16 rows, emits (c*g, row) entries (<=16, exact).
__global__ void __launch_bounds__(256) k_build(const float* __restrict__ lng){
    __shared__ int ss[64], sq[64];
    int tid = threadIdx.x;
    int t = blockIdx.x*256 + tid;
    if (tid < 64){ ss[tid] = 0; sq[tid] = 0; }
    __syncthreads();
    if (t < NCHUNK*64){
        int chunk = t >> 6, b = t & 63;
        float2* dst = g_ent + (size_t)t*16;
        int n = 0, isum = 0, isq = 0;
        #pragma unroll
        for (int r = 0; r < 16; r++){
            int j = chunk*16 + r;
            float c = g_counts[j*B + b];
            int ci = __float2int_rn(c);
            isum += ci; isq += ci*ci;
            if (c != 0.0f){ dst[n] = make_float2(c * lng[j], (float)r); n++; }
        }
        g_ecnt[t] = n;
        atomicAdd(&ss[b], isum);
        atomicAdd(&sq[b], isq);
    }
    __syncthreads();
    if (tid < 64){
        atomicAdd(&g_istat[tid], ss[tid]);
        atomicAdd(&g_istat[64 + tid], sq[tid]);
    }
}

// ---------------- K3: write y (output #1); computes mu/rstd inline ----------
__global__ void __launch_bounds__(256) k3_y(const float* __restrict__ fc,
                                            const float* __restrict__ lng,
                                            const float* __restrict__ lnb,
                                            float* __restrict__ y){
    __shared__ float t[64*65];
    __shared__ float mu_s[64], rs_s[64];
    int tid = threadIdx.x;
    int j0 = blockIdx.x * 64;
    if (tid < 64){
        float mu  = (float)g_istat[tid] / (float)NT;
        float var = (float)g_istat[64 + tid] / (float)NT - mu*mu;
        float rs  = rsqrtf(var + 1e-5f);
        mu_s[tid] = mu; rs_s[tid] = rs;
        if (blockIdx.x == 0){ g_mu[tid] = mu; g_rstd[tid] = rs; }
    }
    #pragma unroll
    for (int i = 0; i < 16; i++){
        int idx = i*256 + tid; int r = idx >> 6, b = idx & 63; int j = j0 + r;
        t[r*65 + b] = (j < NT) ? g_counts[j*B + b] : 0.0f;
    }
    __syncthreads();
    #pragma unroll
    for (int i = 0; i < 16; i++){
        int idx = i*256 + tid; int b = idx >> 6, r = idx & 63; int j = j0 + r;
        if (j < NT)
            y[(size_t)b*NT1 + 1 + j] = (t[r*65 + b] - mu_s[b]) * rs_s[b] * lng[j] + lnb[j];
    }
    if (blockIdx.x == 0 && tid < B) y[(size_t)tid*NT1] = fc[tid] * 0.01f;
}

// ---------------- K4: sparse GEMM1 via compact lists + column-sums ----------
// Grid (8 col-blocks x 50 y-blocks); 128 cols/CTA; 25 chunks of 16 rows each.
__device__ __forceinline__ void k4_stage(float* wbuf, float2* ebuf, int* cbuf,
                                         float* gbuf, float* bbuf,
                                         int cg, int cbase, int tid,
                                         const float* __restrict__ w1,
                                         const float* __restrict__ lng,
                                         const float* __restrict__ lnb){
    // w: 16 rows x 128 floats = 512 x 16B
    #pragma unroll
    for (int i = 0; i < 2; i++){
        int s = i*256 + tid; int r = s >> 5, g = s & 31;
        cpa16(wbuf + r*128 + g*4, w1 + (size_t)(1 + cg*16 + r)*1024 + cbase + g*4);
    }
    // entries: 1024 float2 = 512 x 16B
    #pragma unroll
    for (int i = 0; i < 2; i++){
        int s = i*256 + tid;
        cpa16(ebuf + s*2, g_ent + (size_t)cg*1024 + s*2);
    }
    // counts: 64 ints = 16 x 16B
    if (tid < 16) cpa16(cbuf + tid*4, g_ecnt + cg*64 + tid*4);
    // lng/lnb rows
    if (tid < 16)            cpa4(gbuf + tid, lng + cg*16 + tid);
    else if (tid < 32)       cpa4(bbuf + tid - 16, lnb + cg*16 + tid - 16);
    CP_COMMIT();
}

__global__ void __launch_bounds__(256,3) k4_sparse(const float* __restrict__ w1,
                                                   const float* __restrict__ lng,
                                                   const float* __restrict__ lnb){
    __shared__ __align__(16) float  w_t[2][G4*128];     // 16 KB
    __shared__ __align__(16) float2 ent_s[2][64*16];    // 16 KB
    __shared__ __align__(16) int    cnt_s[2][64];
    __shared__ float gs[2][16], bs[2][16];
    int tid = threadIdx.x, lane = tid & 31, wid = tid >> 5;
    int cbase = blockIdx.x * 128;
    int cg0 = blockIdx.y * CPB;

    unsigned long long acc2[8][2];
    unsigned long long sgw2[2], sbw2[2];
    #pragma unroll
    for (int i = 0; i < 8; i++){ acc2[i][0] = 0ull; acc2[i][1] = 0ull; }
    sgw2[0] = sgw2[1] = 0ull; sbw2[0] = sbw2[1] = 0ull;

    k4_stage(w_t[0], ent_s[0], cnt_s[0], gs[0], bs[0], cg0, cbase, tid, w1, lng, lnb);

    for (int ch = 0; ch < CPB; ch++){
        int cur = ch & 1;
        CP_WAIT0();
        __syncthreads();
        if (ch + 1 < CPB)
            k4_stage(w_t[cur^1], ent_s[cur^1], cnt_s[cur^1], gs[cur^1], bs[cur^1],
                     cg0 + ch + 1, cbase, tid, w1, lng, lnb);

        // colsum: warp wid handles rows wid*2, wid*2+1
        #pragma unroll
        for (int rr = 0; rr < 2; rr++){
            int r = wid*2 + rr;
            ulonglong2 wv = *(const ulonglong2*)&w_t[cur][r*128 + 4*lane];
            unsigned long long gj2, bj2;
            PACK2(gj2, gs[cur][r]); PACK2(bj2, bs[cur][r]);
            FMA2(sgw2[0], gj2, wv.x); FMA2(sgw2[1], gj2, wv.y);
            FMA2(sbw2[0], bj2, wv.x); FMA2(sbw2[1], bj2, wv.y);
        }

        // sparse entries: warp wid owns batches wid*8+i
        #pragma unroll
        for (int i = 0; i < 8; i++){
            int li = wid*8 + i;
            int cnt = cnt_s[cur][li];
            const float2* lp = ent_s[cur] + li*16;
            for (int e = 0; e < cnt; e++){
                float2 en = lp[e];
                int r = __float2int_rn(en.y);
                ulonglong2 wv = *(const ulonglong2*)&w_t[cur][r*128 + 4*lane];
                unsigned long long v2; PACK2(v2, en.x);
                FMA2(acc2[i][0], v2, wv.x);
                FMA2(acc2[i][1], v2, wv.y);
            }
        }
    }

    // accumulate into global accumulators
    #pragma unroll
    for (int i = 0; i < 8; i++){
        float l0,h0,l1,h1;
        UNPK(l0,h0,acc2[i][0]); UNPK(l1,h1,acc2[i][1]);
        float* rowp = g_accum + (wid*8 + i)*1024 + cbase + 4*lane;
        atomicAdd(rowp + 0, l0); atomicAdd(rowp + 1, h0);
        atomicAdd(rowp + 2, l1); atomicAdd(rowp + 3, h1);
    }
    {
        float l0,h0,l1,h1;
        UNPK(l0,h0,sgw2[0]); UNPK(l1,h1,sgw2[1]);
        float* p = g_asgw + cbase + 4*lane;
        atomicAdd(p + 0, l0); atomicAdd(p + 1, h0);
        atomicAdd(p + 2, l1); atomicAdd(p + 3, h1);
        UNPK(l0,h0,sbw2[0]); UNPK(l1,h1,sbw2[1]);
        p = g_asbw + cbase + 4*lane;
        atomicAdd(p + 0, l0); atomicAdd(p + 1, h0);
        atomicAdd(p + 2, l1); atomicAdd(p + 3, h1);
    }
}

// ---------------- K5 fused: finalize + gelu + LayerNorm -> h2 ---------------
__global__ void __launch_bounds__(256) k5_fused(const float* __restrict__ w1,
                                                const float* __restrict__ b1,
                                                const float* __restrict__ fc,
                                                const float* __restrict__ g2,
                                                const float* __restrict__ b2){
    __shared__ float r1[256], r2[256];
    int b = blockIdx.x, tid = threadIdx.x;
    float mu_b = g_mu[b], rs_b = g_rstd[b];
    float fcv = fc[b] * 0.01f;
    float h[4]; float s_sum = 0.0f, s_sq = 0.0f;
    #pragma unroll
    for (int i = 0; i < 4; i++){
        int k = i*256 + tid;
        float logit = fcv * w1[k] + g_asbw[k] - mu_b*rs_b*g_asgw[k]
                    + rs_b * g_accum[b*1024 + k] + b1[k];
        h[i] = gelu_exact(logit);
        s_sum += h[i]; s_sq += h[i]*h[i];
    }
    r1[tid] = s_sum; r2[tid] = s_sq; __syncthreads();
    for (int o = 128; o > 0; o >>= 1){
        if (tid < o){ r1[tid] += r1[tid+o]; r2[tid] += r2[tid+o]; }
        __syncthreads();
    }
    float mu = r1[0] * (1.0f/1024.0f);
    float var = r2[0] * (1.0f/1024.0f) - mu*mu;
    float rs = rsqrtf(var + 1e-5f);
    #pragma unroll
    for (int i = 0; i < 4; i++){
        int k = i*256 + tid;
        g_h2[b*1024 + k] = (h[i] - mu)*rs*g2[k] + b2[k];
    }
}

// ---------------- small GEMM: split-K partial + reduce ----------------------
template<int K, int N, int KPER>
__global__ void __launch_bounds__(256) sg_part(const float* __restrict__ A,
                                               const float* __restrict__ W,
                                               float* __restrict__ P){
    __shared__ float a_s[64*32];
    __shared__ float w_s[32*64];
    int tid = threadIdx.x, lane = tid & 31, wid = tid >> 5;
    int cbase = blockIdx.x*64, kbase = blockIdx.y*KPER;
    float acc[8][2] = {};
    for (int kc = kbase; kc < kbase + KPER; kc += 32){
        #pragma unroll
        for (int i = 0; i < 8; i++){
            int idx = i*256 + tid; int b = idx >> 5, kk = idx & 31;
            a_s[b*32 + kk] = A[b*K + kc + kk];
        }
        #pragma unroll
        for (int i = 0; i < 8; i++){
            int idx = i*256 + tid; int kk = idx >> 6, c = idx & 63;
            w_s[kk*64 + c] = W[(size_t)(kc + kk)*N + cbase + c];
        }
        __syncthreads();
        #pragma unroll
        for (int kk = 0; kk < 32; kk++){
            float av[8], wv0, wv1;
            #pragma unroll
            for (int i = 0; i < 8; i++) av[i] = a_s[(wid*8 + i)*32 + kk];
            wv0 = w_s[kk*64 + lane]; wv1 = w_s[kk*64 + lane + 32];
            #pragma unroll
            for (int i = 0; i < 8; i++){
                acc[i][0] += av[i]*wv0;
                acc[i][1] += av[i]*wv1;
            }
        }
        __syncthreads();
    }
    #pragma unroll
    for (int i = 0; i < 8; i++){
        P[blockIdx.y*(64*N) + (wid*8 + i)*N + cbase + lane]      = acc[i][0];
        P[blockIdx.y*(64*N) + (wid*8 + i)*N + cbase + lane + 32] = acc[i][1];
    }
}

template<int S, int N, bool ACT>
__global__ void sg_reduce(const float* __restrict__ P, const float* __restrict__ bias,
                          float* __restrict__ out, float* __restrict__ out2){
    int i = blockIdx.x*256 + threadIdx.x;
    if (i >= 64*N) return;
    float s = bias[i % N];
    #pragma unroll
    for (int p = 0; p < S; p++) s += P[p*64*N + i];
    if (ACT) s = gelu_exact(s);
    out[i] = s;
    if (out2) out2[i] = s;
}

// ---------------- K10: decoder GEMM [64x1024]@[1024x20001] ------------------
#define KC10 16
__global__ void __launch_bounds__(256,2) k10_part(const float* __restrict__ wd2,
                                                  float* __restrict__ P){
    extern __shared__ __align__(16) float dsm[];
    float* w_s  = dsm;          // [2][16*272]
    float* d_sm = dsm + 8704;   // [2][16*130]
    int tid = threadIdx.x, lane = tid & 31, wid = tid >> 5;
    int cbase = blockIdx.x * 272;
    int kbase = blockIdx.y * 256;

    unsigned long long acc[8][4];
    float accx[8];
    #pragma unroll
    for (int i = 0; i < 8; i++){
        accx[i] = 0.0f;
        #pragma unroll
        for (int j = 0; j < 4; j++) acc[i][j] = 0ull;
    }
    float dreg[4];

    {
        #pragma unroll
        for (int i = 0; i < 17; i++){
            int idx = i*256 + tid; int r = idx / 272, c = idx - r*272;
            int gc = cbase + c;
            float* dst = w_s + r*272 + c;
            if (gc < NT1) cpa4(dst, wd2 + (size_t)(kbase + r)*NT1 + gc);
            else *dst = 0.0f;
        }
        CP_COMMIT();
        #pragma unroll
        for (int i = 0; i < 4; i++){
            int idx = i*256 + tid; int b = idx >> 4, k = idx & 15;
            dreg[i] = g_dd[b*1024 + kbase + k];
        }
        #pragma unroll
        for (int i = 0; i < 4; i++){
            int idx = i*256 + tid; int b = idx >> 4, k = idx & 15;
            d_sm[k*130 + 2*b] = dreg[i]; d_sm[k*130 + 2*b + 1] = dreg[i];
        }
    }

    for (int ch = 0; ch < 16; ch++){
        int cur = ch & 1;
        CP_WAIT0();
        __syncthreads();
        if (ch + 1 < 16){
            int kpos = kbase + (ch + 1)*KC10;
            float* wdst = w_s + (cur^1)*4352;
            #pragma unroll
            for (int i = 0; i < 17; i++){
                int idx = i*256 + tid; int r = idx / 272, c = idx - r*272;
                int gc = cbase + c;
                float* dst = wdst + r*272 + c;
                if (gc < NT1) cpa4(dst, wd2 + (size_t)(kpos + r)*NT1 + gc);
                else *dst = 0.0f;
            }
            CP_COMMIT();
            #pragma unroll
            for (int i = 0; i < 4; i++){
                int idx = i*256 + tid; int b = idx >> 4, k = idx & 15;
                dreg[i] = g_dd[b*1024 + kpos + k];
            }
        }
        const float* wb = w_s + cur*4352;
        const float* db = d_sm + cur*2080;
        #pragma unroll 4
        for (int k = 0; k < KC10; k++){
            const float* wrow = wb + k*272;
            ulonglong2 wg0 = *(const ulonglong2*)(wrow + 4*lane);
            ulonglong2 wg1 = *(const ulonglong2*)(wrow + 128 + 4*lane);
            float wex = wrow[256 + (lane & 15)];
            const float* drow = db + k*130;
            #pragma unroll
            for (int i = 0; i < 8; i++){
                int b = wid*8 + i;
                unsigned long long dv = *(const unsigned long long*)(drow + 2*b);
                FMA2(acc[i][0], dv, wg0.x); FMA2(acc[i][1], dv, wg0.y);
                FMA2(acc[i][2], dv, wg1.x); FMA2(acc[i][3], dv, wg1.y);
                float dsc = __uint_as_float((unsigned)dv);
                accx[i] = fmaf(dsc, wex, accx[i]);
            }
        }
        if (ch + 1 < 16){
            float* ddst = d_sm + (cur^1)*2080;
            #pragma unroll
            for (int i = 0; i < 4; i++){
                int idx = i*256 + tid; int b = idx >> 4, k = idx & 15;
                ddst[k*130 + 2*b] = dreg[i]; ddst[k*130 + 2*b + 1] = dreg[i];
            }
        }
    }

    size_t obase = (size_t)blockIdx.y * (B*NTP);
    #pragma unroll
    for (int i = 0; i < 8; i++){
        float* rowp = P + obase + (size_t)(wid*8 + i)*NTP + cbase;
        float l0, h0, l1, h1;
        UNPK(l0,h0,acc[i][0]); UNPK(l1,h1,acc[i][1]);
        *(float4*)(rowp + 4*lane) = make_float4(l0, h0, l1, h1);
        UNPK(l0,h0,acc[i][2]); UNPK(l1,h1,acc[i][3]);
        *(float4*)(rowp + 128 + 4*lane) = make_float4(l0, h0, l1, h1);
        if (lane < 16) rowp[256 + lane] = accx[i];
    }
}

__global__ void k10_reduce(const float* __restrict__ P, const float* __restrict__ bd2,
                           float* __restrict__ dec){
    int i = blockIdx.x*256 + threadIdx.x;
    if (i >= B*NT1) return;
    int b = i / NT1;
    int c = i - b*NT1;
    float s = bd2[c];
    #pragma unroll
    for (int p = 0; p < 4; p++) s += P[(size_t)p*(B*NTP) + (size_t)b*NTP + c];
    dec[i] = s;
}

// ---------------- launch -----------------------------------------------------
extern "C" void kernel_launch(void* const* d_in, const int* in_sizes, int n_in,
                              void* d_out, int out_size){
    const int*   tags = (const int*)  d_in[0];
    const float* fc   = (const float*)d_in[1];
    const float* lng  = (const float*)d_in[2];
    const float* lnb  = (const float*)d_in[3];
    const float* w1   = (const float*)d_in[4];
    const float* b1   = (const float*)d_in[5];
    const float* ln2g = (const float*)d_in[6];
    const float* ln2b = (const float*)d_in[7];
    const float* we1  = (const float*)d_in[8];
    const float* be1  = (const float*)d_in[9];
    const float* we2  = (const float*)d_in[10];
    const float* be2  = (const float*)d_in[11];
    const float* wd1  = (const float*)d_in[12];
    const float* bd1  = (const float*)d_in[13];
    const float* wd2  = (const float*)d_in[14];
    const float* bd2  = (const float*)d_in[15];
    float* out = (float*)d_out;

    float *p_counts, *p_h2, *p_h3, *p_enc, *p_dd, *p_pbuf, *p_pacc;
    cudaGetSymbolAddress((void**)&p_counts, g_counts);
    cudaGetSymbolAddress((void**)&p_h2,     g_h2);
    cudaGetSymbolAddress((void**)&p_h3,     g_h3);
    cudaGetSymbolAddress((void**)&p_enc,    g_encb);
    cudaGetSymbolAddress((void**)&p_dd,     g_dd);
    cudaGetSymbolAddress((void**)&p_pbuf,   g_pbuf);
    cudaGetSymbolAddress((void**)&p_pacc,   g_pacc);

    static int smem_set = 0;
    if (!smem_set){
        cudaFuncSetAttribute(k10_part, cudaFuncAttributeMaxDynamicSharedMemorySize, 51456);
        smem_set = 1;
    }

    cudaMemsetAsync(p_counts, 0, (size_t)NT*B*sizeof(float));
    k1_scatter<<<32, 256>>>(tags);
    k_build<<<313, 256>>>(lng);
    k3_y<<<313, 256>>>(fc, lng, lnb, out);
    k4_sparse<<<dim3(8, RCY), 256>>>(w1, lng, lnb);
    k5_fused<<<64, 256>>>(w1, b1, fc, ln2g, ln2b);

    // h2 @ we1 (1024->1024) + gelu
    sg_part<1024, 1024, 32><<<dim3(16, 32), 256>>>(p_h2, we1, p_pbuf);
    sg_reduce<32, 1024, true><<<256, 256>>>(p_pbuf, be1, p_h3, (float*)0);
    // h3 @ we2 (1024->256) -> enc (output #2)
    sg_part<1024, 256, 32><<<dim3(4, 32), 256>>>(p_h3, we2, p_pbuf);
    sg_reduce<32, 256, false><<<64, 256>>>(p_pbuf, be2, out + ENC_OFF, p_enc);
    // enc @ wd1 (256->1024) + gelu
    sg_part<256, 1024, 32><<<dim3(16, 8), 256>>>(p_enc, wd1, p_pbuf);
    sg_reduce<8, 1024, true><<<256, 256>>>(p_pbuf, bd1, p_dd, (float*)0);

    // dd @ wd2 (1024->20001) -> dec (output #3)
    k10_part<<<dim3(74, 4), 256, 51456>>>(wd2, p_pacc);
    k10_reduce<<<5001, 256>>>(p_pacc, bd2, out + DEC_OFF);
}

// round 10
// speedup vs baseline: 1.2398x; 1.2398x over previous
#include <cuda_runtime.h>
#include <cuda_bf16.h>
#include <math.h>

#define B   64
#define NT  20000
#define NT1 20001
#define H4  1024
#define HD  256
#define Y_SZ    (B*NT1)
#define ENC_OFF Y_SZ
#define DEC_OFF (Y_SZ + B*HD)

// k4 sparse GEMM config
#define NCHUNK 1250          // 16-row chunks over 20000 tags
#define RCY  50              // y-blocks
#define CPB  25              // chunks per y-block
#define G4   16              // rows per chunk

// ---------------- scratch (device globals; no allocations) -----------------
__device__ float    g_counts[NT*B];              // [tag][batch] (row-chunk contiguous)
__device__ unsigned g_rmask[NCHUNK*64];          // per (chunk,b): 16-bit active-row mask
__device__ int      g_istat[128];                // [0:64) sum, [64:128) sumsq
__device__ float    g_accum[B*H4];               // k4 atomic accumulator (L2-resident)
__device__ float    g_asgw[H4], g_asbw[H4];      // column-sum accumulators
__device__ float    g_h2[B*H4], g_h3[B*H4], g_encb[B*HD], g_dd[B*H4];
__device__ float    g_pbuf[32*B*H4];             // small-GEMM split-K partials

__device__ __forceinline__ float gelu_exact(float x){
    return 0.5f * x * (1.0f + erff(x * 0.70710678118654752f));
}
__device__ __forceinline__ void cpa16(void* d, const void* s){
    unsigned a = (unsigned)__cvta_generic_to_shared(d);
    asm volatile("cp.async.ca.shared.global [%0], [%1], 16;" :: "r"(a), "l"(s));
}
__device__ __forceinline__ void cpa4(void* d, const void* s){
    unsigned a = (unsigned)__cvta_generic_to_shared(d);
    asm volatile("cp.async.ca.shared.global [%0], [%1], 4;" :: "r"(a), "l"(s));
}
#define CP_COMMIT() asm volatile("cp.async.commit_group;" ::: "memory")
#define CP_WAIT0()  asm volatile("cp.async.wait_group 0;" ::: "memory")
#define FMA2(a,x,y) asm("fma.rn.f32x2 %0, %1, %2, %0;" : "+l"(a) : "l"(x), "l"(y))
#define PACK2(o,f)  asm("mov.b64 %0, {%1,%1};" : "=l"(o) : "f"(f))
#define UNPK(l,h,a) asm("mov.b64 {%0,%1}, %2;" : "=f"(l), "=f"(h) : "l"(a))

// ---------------- K1: scatter counts + row-masks + zero accums + seed dec ---
__global__ void k1_scatter(const int* __restrict__ tags,
                           const float* __restrict__ bd2,
                           float* __restrict__ dec){
    int p = blockIdx.x*256 + threadIdx.x;       // 8192 threads
    if (blockIdx.x == 0 && threadIdx.x < 128) g_istat[threadIdx.x] = 0;
    for (int z = p; z < B*H4; z += 8192) g_accum[z] = 0.0f;
    if (p < H4){ g_asgw[p] = 0.0f; g_asbw[p] = 0.0f; }
    // seed decoder output with bias (k10 atomically accumulates onto it)
    for (int c = p; c < NT1; c += 8192){
        float v = bd2[c];
        #pragma unroll 4
        for (int b = 0; b < B; b++) dec[(size_t)b*NT1 + c] = v;
    }
    int b = p >> 7;
    const int* t = tags + p*16;
    int v[16];
    #pragma unroll
    for (int i = 0; i < 16; i++) v[i] = t[i];
    #pragma unroll
    for (int i = 0; i < 16; i++){
        bool dup = false;
        #pragma unroll
        for (int s = 0; s < 16; s++) if (s < i) dup = dup || (v[s] == v[i]);
        if (!dup){
            atomicAdd(&g_counts[v[i]*B + b], 1.0f);
            atomicOr(&g_rmask[(v[i] >> 4)*64 + b], 1u << (v[i] & 15));
        }
    }
}

// ---------------- K2: per-batch stats (integer-exact, deterministic) --------
__global__ void k2a_stats(){
    int tid = threadIdx.x;
    int b = tid & 63;
    int s = 0, sq = 0;
    for (int idx = blockIdx.x*256 + tid; idx < NT*B; idx += 160*256){
        int c = __float2int_rn(g_counts[idx]);
        s += c; sq += c*c;
    }
    atomicAdd(&g_istat[b], s);
    atomicAdd(&g_istat[64 + b], sq);
}

// ---------------- K3: write y (output #1); computes mu/rstd inline ----------
__global__ void __launch_bounds__(256) k3_y(const float* __restrict__ fc,
                                            const float* __restrict__ lng,
                                            const float* __restrict__ lnb,
                                            float* __restrict__ y){
    __shared__ float t[64*65];
    __shared__ float mu_s[64], rs_s[64];
    int tid = threadIdx.x;
    int j0 = blockIdx.x * 64;
    if (tid < 64){
        float mu  = (float)g_istat[tid] / (float)NT;
        float var = (float)g_istat[64 + tid] / (float)NT - mu*mu;
        mu_s[tid] = mu; rs_s[tid] = rsqrtf(var + 1e-5f);
    }
    #pragma unroll
    for (int i = 0; i < 16; i++){
        int idx = i*256 + tid; int r = idx >> 6, b = idx & 63; int j = j0 + r;
        t[r*65 + b] = (j < NT) ? g_counts[j*B + b] : 0.0f;
    }
    __syncthreads();
    #pragma unroll
    for (int i = 0; i < 16; i++){
        int idx = i*256 + tid; int b = idx >> 6, r = idx & 63; int j = j0 + r;
        if (j < NT)
            y[(size_t)b*NT1 + 1 + j] = (t[r*65 + b] - mu_s[b]) * rs_s[b] * lng[j] + lnb[j];
    }
    if (blockIdx.x == 0 && tid < B) y[(size_t)tid*NT1] = fc[tid] * 0.01f;
}

// ---------------- K4: sparse GEMM1 via row-masks + column-sums --------------
// Grid (8 col x 50 row) = 400 CTAs, 3/SM. 128 cols/CTA, 25 chunks of 16 rows.
__device__ __forceinline__ void k4_stage(float* wbuf, float* cbuf, unsigned* mbuf,
                                         float* gbuf, float* bbuf,
                                         int cg, int cbase, int tid,
                                         const float* __restrict__ w1,
                                         const float* __restrict__ lng,
                                         const float* __restrict__ lnb){
    #pragma unroll
    for (int i = 0; i < 2; i++){
        int s = i*256 + tid; int r = s >> 5, g = s & 31;
        cpa16(wbuf + r*128 + g*4, w1 + (size_t)(1 + cg*16 + r)*1024 + cbase + g*4);
    }
    cpa16(cbuf + tid*4, g_counts + (size_t)cg*1024 + tid*4);   // 16x64 contiguous
    if (tid < 16)      cpa16(mbuf + tid*4, g_rmask + cg*64 + tid*4);
    if (tid < 16)      cpa4(gbuf + tid, lng + cg*16 + tid);
    else if (tid < 32) cpa4(bbuf + tid - 16, lnb + cg*16 + tid - 16);
    CP_COMMIT();
}

__global__ void __launch_bounds__(256,3) k4_sparse(const float* __restrict__ w1,
                                                   const float* __restrict__ lng,
                                                   const float* __restrict__ lnb){
    __shared__ __align__(16) float    w_t[2][G4*128];   // 16 KB
    __shared__ __align__(16) float    cnt_s[2][G4*64];  // 8 KB
    __shared__ __align__(16) unsigned mk_s[2][64];
    __shared__ float gs[2][16], bs[2][16];
    int tid = threadIdx.x, lane = tid & 31, wid = tid >> 5;
    int cbase = blockIdx.x * 128;
    int cg0 = blockIdx.y * CPB;

    unsigned long long acc2[8][2];
    unsigned long long sgw2[2], sbw2[2];
    #pragma unroll
    for (int i = 0; i < 8; i++){ acc2[i][0] = 0ull; acc2[i][1] = 0ull; }
    sgw2[0] = sgw2[1] = 0ull; sbw2[0] = sbw2[1] = 0ull;

    k4_stage(w_t[0], cnt_s[0], mk_s[0], gs[0], bs[0], cg0, cbase, tid, w1, lng, lnb);

    for (int ch = 0; ch < CPB; ch++){
        int cur = ch & 1;
        CP_WAIT0();
        __syncthreads();
        if (ch + 1 < CPB)
            k4_stage(w_t[cur^1], cnt_s[cur^1], mk_s[cur^1], gs[cur^1], bs[cur^1],
                     cg0 + ch + 1, cbase, tid, w1, lng, lnb);

        // balanced colsum: warp wid owns rows wid*2, wid*2+1
        #pragma unroll
        for (int rr = 0; rr < 2; rr++){
            int r = wid*2 + rr;
            ulonglong2 wv = *(const ulonglong2*)&w_t[cur][r*128 + 4*lane];
            unsigned long long gj2, bj2;
            PACK2(gj2, gs[cur][r]); PACK2(bj2, bs[cur][r]);
            FMA2(sgw2[0], gj2, wv.x); FMA2(sgw2[1], gj2, wv.y);
            FMA2(sbw2[0], bj2, wv.x); FMA2(sbw2[1], bj2, wv.y);
        }

        // sparse part: masks for this warp's 8 batches (broadcast LDS, uniform)
        unsigned bm[8], am = 0;
        #pragma unroll
        for (int i = 0; i < 8; i++){ bm[i] = mk_s[cur][wid*8 + i]; am |= bm[i]; }
        while (am){
            int r = __ffs(am) - 1; am &= am - 1;
            ulonglong2 wv = *(const ulonglong2*)&w_t[cur][r*128 + 4*lane];
            float gj = gs[cur][r];
            #pragma unroll
            for (int i = 0; i < 8; i++){
                if ((bm[i] >> r) & 1){              // warp-uniform
                    float c = cnt_s[cur][r*64 + wid*8 + i];
                    float v = c * gj;
                    unsigned long long v2; PACK2(v2, v);
                    FMA2(acc2[i][0], v2, wv.x);
                    FMA2(acc2[i][1], v2, wv.y);
                }
            }
        }
    }

    #pragma unroll
    for (int i = 0; i < 8; i++){
        float l0,h0,l1,h1;
        UNPK(l0,h0,acc2[i][0]); UNPK(l1,h1,acc2[i][1]);
        float* rowp = g_accum + (wid*8 + i)*1024 + cbase + 4*lane;
        atomicAdd(rowp + 0, l0); atomicAdd(rowp + 1, h0);
        atomicAdd(rowp + 2, l1); atomicAdd(rowp + 3, h1);
    }
    {
        float l0,h0,l1,h1;
        UNPK(l0,h0,sgw2[0]); UNPK(l1,h1,sgw2[1]);
        float* p = g_asgw + cbase + 4*lane;
        atomicAdd(p + 0, l0); atomicAdd(p + 1, h0);
        atomicAdd(p + 2, l1); atomicAdd(p + 3, h1);
        UNPK(l0,h0,sbw2[0]); UNPK(l1,h1,sbw2[1]);
        p = g_asbw + cbase + 4*lane;
        atomicAdd(p + 0, l0); atomicAdd(p + 1, h0);
        atomicAdd(p + 2, l1); atomicAdd(p + 3, h1);
    }
}

// ---------------- K5 fused: finalize + gelu + LayerNorm -> h2 ---------------
__global__ void __launch_bounds__(256) k5_fused(const float* __restrict__ w1,
                                                const float* __restrict__ b1,
                                                const float* __restrict__ fc,
                                                const float* __restrict__ g2,
                                                const float* __restrict__ b2){
    __shared__ float r1[256], r2[256];
    int b = blockIdx.x, tid = threadIdx.x;
    float mu_b  = (float)g_istat[b] / (float)NT;
    float var_b = (float)g_istat[64 + b] / (float)NT - mu_b*mu_b;
    float rs_b  = rsqrtf(var_b + 1e-5f);
    float fcv = fc[b] * 0.01f;
    float h[4]; float s_sum = 0.0f, s_sq = 0.0f;
    #pragma unroll
    for (int i = 0; i < 4; i++){
        int k = i*256 + tid;
        float logit = fcv * w1[k] + g_asbw[k] - mu_b*rs_b*g_asgw[k]
                    + rs_b * g_accum[b*1024 + k] + b1[k];
        h[i] = gelu_exact(logit);
        s_sum += h[i]; s_sq += h[i]*h[i];
    }
    r1[tid] = s_sum; r2[tid] = s_sq; __syncthreads();
    for (int o = 128; o > 0; o >>= 1){
        if (tid < o){ r1[tid] += r1[tid+o]; r2[tid] += r2[tid+o]; }
        __syncthreads();
    }
    float mu = r1[0] * (1.0f/1024.0f);
    float var = r2[0] * (1.0f/1024.0f) - mu*mu;
    float rs = rsqrtf(var + 1e-5f);
    #pragma unroll
    for (int i = 0; i < 4; i++){
        int k = i*256 + tid;
        g_h2[b*1024 + k] = (h[i] - mu)*rs*g2[k] + b2[k];
    }
}

// ---------------- small GEMM: split-K partial + reduce ----------------------
template<int K, int N, int KPER>
__global__ void __launch_bounds__(256) sg_part(const float* __restrict__ A,
                                               const float* __restrict__ W,
                                               float* __restrict__ P){
    __shared__ float a_s[64*32];
    __shared__ float w_s[32*64];
    int tid = threadIdx.x, lane = tid & 31, wid = tid >> 5;
    int cbase = blockIdx.x*64, kbase = blockIdx.y*KPER;
    float acc[8][2] = {};
    for (int kc = kbase; kc < kbase + KPER; kc += 32){
        #pragma unroll
        for (int i = 0; i < 8; i++){
            int idx = i*256 + tid; int b = idx >> 5, kk = idx & 31;
            a_s[b*32 + kk] = A[b*K + kc + kk];
        }
        #pragma unroll
        for (int i = 0; i < 8; i++){
            int idx = i*256 + tid; int kk = idx >> 6, c = idx & 63;
            w_s[kk*64 + c] = W[(size_t)(kc + kk)*N + cbase + c];
        }
        __syncthreads();
        #pragma unroll
        for (int kk = 0; kk < 32; kk++){
            float av[8], wv0, wv1;
            #pragma unroll
            for (int i = 0; i < 8; i++) av[i] = a_s[(wid*8 + i)*32 + kk];
            wv0 = w_s[kk*64 + lane]; wv1 = w_s[kk*64 + lane + 32];
            #pragma unroll
            for (int i = 0; i < 8; i++){
                acc[i][0] += av[i]*wv0;
                acc[i][1] += av[i]*wv1;
            }
        }
        __syncthreads();
    }
    #pragma unroll
    for (int i = 0; i < 8; i++){
        P[blockIdx.y*(64*N) + (wid*8 + i)*N + cbase + lane]      = acc[i][0];
        P[blockIdx.y*(64*N) + (wid*8 + i)*N + cbase + lane + 32] = acc[i][1];
    }
}

template<int S, int N, bool ACT>
__global__ void sg_reduce(const float* __restrict__ P, const float* __restrict__ bias,
                          float* __restrict__ out, float* __restrict__ out2){
    int i = blockIdx.x*256 + threadIdx.x;
    if (i >= 64*N) return;
    float s = bias[i % N];
    #pragma unroll
    for (int p = 0; p < S; p++) s += P[p*64*N + i];
    if (ACT) s = gelu_exact(s);
    out[i] = s;
    if (out2) out2[i] = s;
}

// ---------------- K10: decoder GEMM, atomic-accumulate into dec -------------
#define KC10 16
__global__ void __launch_bounds__(256,2) k10_part(const float* __restrict__ wd2,
                                                  float* __restrict__ dec){
    extern __shared__ __align__(16) float dsm[];
    float* w_s  = dsm;          // [2][16*272]
    float* d_sm = dsm + 8704;   // [2][16*130]
    int tid = threadIdx.x, lane = tid & 31, wid = tid >> 5;
    int cbase = blockIdx.x * 272;
    int kbase = blockIdx.y * 256;

    unsigned long long acc[8][4];
    float accx[8];
    #pragma unroll
    for (int i = 0; i < 8; i++){
        accx[i] = 0.0f;
        #pragma unroll
        for (int j = 0; j < 4; j++) acc[i][j] = 0ull;
    }
    float dreg[4];

    {
        #pragma unroll
        for (int i = 0; i < 17; i++){
            int idx = i*256 + tid; int r = idx / 272, c = idx - r*272;
            int gc = cbase + c;
            float* dst = w_s + r*272 + c;
            if (gc < NT1) cpa4(dst, wd2 + (size_t)(kbase + r)*NT1 + gc);
            else *dst = 0.0f;
        }
        CP_COMMIT();
        #pragma unroll
        for (int i = 0; i < 4; i++){
            int idx = i*256 + tid; int b = idx >> 4, k = idx & 15;
            dreg[i] = g_dd[b*1024 + kbase + k];
        }
        #pragma unroll
        for (int i = 0; i < 4; i++){
            int idx = i*256 + tid; int b = idx >> 4, k = idx & 15;
            d_sm[k*130 + 2*b] = dreg[i]; d_sm[k*130 + 2*b + 1] = dreg[i];
        }
    }

    for (int ch = 0; ch < 16; ch++){
        int cur = ch & 1;
        CP_WAIT0();
        __syncthreads();
        if (ch + 1 < 16){
            int kpos = kbase + (ch + 1)*KC10;
            float* wdst = w_s + (cur^1)*4352;
            #pragma unroll
            for (int i = 0; i < 17; i++){
                int idx = i*256 + tid; int r = idx / 272, c = idx - r*272;
                int gc = cbase + c;
                float* dst = wdst + r*272 + c;
                if (gc < NT1) cpa4(dst, wd2 + (size_t)(kpos + r)*NT1 + gc);
                else *dst = 0.0f;
            }
            CP_COMMIT();
            #pragma unroll
            for (int i = 0; i < 4; i++){
                int idx = i*256 + tid; int b = idx >> 4, k = idx & 15;
                dreg[i] = g_dd[b*1024 + kpos + k];
            }
        }
        const float* wb = w_s + cur*4352;
        const float* db = d_sm + cur*2080;
        #pragma unroll 4
        for (int k = 0; k < KC10; k++){
            const float* wrow = wb + k*272;
            ulonglong2 wg0 = *(const ulonglong2*)(wrow + 4*lane);
            ulonglong2 wg1 = *(const ulonglong2*)(wrow + 128 + 4*lane);
            float wex = wrow[256 + (lane & 15)];
            const float* drow = db + k*130;
            #pragma unroll
            for (int i = 0; i < 8; i++){
                int b = wid*8 + i;
                unsigned long long dv = *(const unsigned long long*)(drow + 2*b);
                FMA2(acc[i][0], dv, wg0.x); FMA2(acc[i][1], dv, wg0.y);
                FMA2(acc[i][2], dv, wg1.x); FMA2(acc[i][3], dv, wg1.y);
                float dsc = __uint_as_float((unsigned)dv);
                accx[i] = fmaf(dsc, wex, accx[i]);
            }
        }
        if (ch + 1 < 16){
            float* ddst = d_sm + (cur^1)*2080;
            #pragma unroll
            for (int i = 0; i < 4; i++){
                int idx = i*256 + tid; int b = idx >> 4, k = idx & 15;
                ddst[k*130 + 2*b] = dreg[i]; ddst[k*130 + 2*b + 1] = dreg[i];
            }
        }
    }

    // atomic accumulate into bias-seeded dec
    #pragma unroll
    for (int i = 0; i < 8; i++){
        float* rowp = dec + (size_t)(wid*8 + i)*NT1;
        float l0, h0, l1, h1;
        int c0 = cbase + 4*lane;
        UNPK(l0,h0,acc[i][0]); UNPK(l1,h1,acc[i][1]);
        atomicAdd(rowp + c0,     l0); atomicAdd(rowp + c0 + 1, h0);
        atomicAdd(rowp + c0 + 2, l1); atomicAdd(rowp + c0 + 3, h1);
        int c1 = c0 + 128;
        UNPK(l0,h0,acc[i][2]); UNPK(l1,h1,acc[i][3]);
        if (c1     < NT1) atomicAdd(rowp + c1,     l0);
        if (c1 + 1 < NT1) atomicAdd(rowp + c1 + 1, h0);
        if (c1 + 2 < NT1) atomicAdd(rowp + c1 + 2, l1);
        if (c1 + 3 < NT1) atomicAdd(rowp + c1 + 3, h1);
        int c2 = cbase + 256 + lane;
        if (lane < 16 && c2 < NT1) atomicAdd(rowp + c2, accx[i]);
    }
}

// ---------------- launch -----------------------------------------------------
extern "C" void kernel_launch(void* const* d_in, const int* in_sizes, int n_in,
                              void* d_out, int out_size){
    const int*   tags = (const int*)  d_in[0];
    const float* fc   = (const float*)d_in[1];
    const float* lng  = (const float*)d_in[2];
    const float* lnb  = (const float*)d_in[3];
    const float* w1   = (const float*)d_in[4];
    const float* b1   = (const float*)d_in[5];
    const float* ln2g = (const float*)d_in[6];
    const float* ln2b = (const float*)d_in[7];
    const float* we1  = (const float*)d_in[8];
    const float* be1  = (const float*)d_in[9];
    const float* we2  = (const float*)d_in[10];
    const float* be2  = (const float*)d_in[11];
    const float* wd1  = (const float*)d_in[12];
    const float* bd1  = (const float*)d_in[13];
    const float* wd2  = (const float*)d_in[14];
    const float* bd2  = (const float*)d_in[15];
    float* out = (float*)d_out;

    float *p_counts, *p_h2, *p_h3, *p_enc, *p_dd, *p_pbuf;
    unsigned* p_rmask;
    cudaGetSymbolAddress((void**)&p_counts, g_counts);
    cudaGetSymbolAddress((void**)&p_rmask,  g_rmask);
    cudaGetSymbolAddress((void**)&p_h2,     g_h2);
    cudaGetSymbolAddress((void**)&p_h3,     g_h3);
    cudaGetSymbolAddress((void**)&p_enc,    g_encb);
    cudaGetSymbolAddress((void**)&p_dd,     g_dd);
    cudaGetSymbolAddress((void**)&p_pbuf,   g_pbuf);

    static int smem_set = 0;
    if (!smem_set){
        cudaFuncSetAttribute(k10_part, cudaFuncAttributeMaxDynamicSharedMemorySize, 51456);
        smem_set = 1;
    }

    cudaMemsetAsync(p_counts, 0, (size_t)NT*B*sizeof(float));
    cudaMemsetAsync(p_rmask,  0, (size_t)NCHUNK*64*sizeof(unsigned));
    k1_scatter<<<32, 256>>>(tags, bd2, out + DEC_OFF);
    k2a_stats<<<160, 256>>>();
    k3_y<<<313, 256>>>(fc, lng, lnb, out);
    k4_sparse<<<dim3(8, RCY), 256>>>(w1, lng, lnb);
    k5_fused<<<64, 256>>>(w1, b1, fc, ln2g, ln2b);

    // h2 @ we1 (1024->1024) + gelu
    sg_part<1024, 1024, 32><<<dim3(16, 32), 256>>>(p_h2, we1, p_pbuf);
    sg_reduce<32, 1024, true><<<256, 256>>>(p_pbuf, be1, p_h3, (float*)0);
    // h3 @ we2 (1024->256) -> enc (output #2)
    sg_part<1024, 256, 32><<<dim3(4, 32), 256>>>(p_h3, we2, p_pbuf);
    sg_reduce<32, 256, false><<<64, 256>>>(p_pbuf, be2, out + ENC_OFF, p_enc);
    // enc @ wd1 (256->1024) + gelu
    sg_part<256, 1024, 32><<<dim3(16, 8), 256>>>(p_enc, wd1, p_pbuf);
    sg_reduce<8, 1024, true><<<256, 256>>>(p_pbuf, bd1, p_dd, (float*)0);

    // dd @ wd2 (1024->20001) -> dec (output #3), atomic onto bias-seeded dec
    k10_part<<<dim3(74, 4), 256, 51456>>>(wd2, out + DEC_OFF);
}

// round 11
// speedup vs baseline: 2.3580x; 1.9019x over previous
#include <cuda_runtime.h>
#include <cuda_bf16.h>
#include <math.h>

#define B   64
#define NT  20000
#define NT1 20001
#define H4  1024
#define HD  256
#define Y_SZ    (B*NT1)
#define ENC_OFF Y_SZ
#define DEC_OFF (Y_SZ + B*HD)

// ---------------- scratch (device globals; no allocations) -----------------
__device__ float g_counts[NT*B];                 // [tag][batch]
__device__ int   g_istat[128];                   // [0:64) sum, [64:128) sumsq
__device__ float g_accum[B*H4];                  // GEMM1 split-K accumulator
__device__ float g_h2[B*H4], g_h3[B*H4], g_encb[B*HD];
__device__ __align__(16) __nv_bfloat16 g_ddh[B*H4], g_ddl[B*H4];
__device__ float g_pbuf[32*B*H4];                // small-GEMM split-K partials

__device__ __forceinline__ float gelu_exact(float x){
    return 0.5f * x * (1.0f + erff(x * 0.70710678118654752f));
}

// ---------------- mma.sync helpers (m16n8k16 bf16, row.col) ------------------
__device__ __forceinline__ void ldm_x4(unsigned r[4], unsigned addr){
    asm volatile("ldmatrix.sync.aligned.m8n8.x4.shared.b16 {%0,%1,%2,%3}, [%4];"
        : "=r"(r[0]),"=r"(r[1]),"=r"(r[2]),"=r"(r[3]) : "r"(addr));
}
__device__ __forceinline__ void ldm_x2t(unsigned r[2], unsigned addr){
    asm volatile("ldmatrix.sync.aligned.m8n8.x2.trans.shared.b16 {%0,%1}, [%2];"
        : "=r"(r[0]),"=r"(r[1]) : "r"(addr));
}
__device__ __forceinline__ void mma_bf(float c[4], const unsigned a[4], const unsigned b[2]){
    asm volatile("mma.sync.aligned.m16n8k16.row.col.f32.bf16.bf16.f32 "
        "{%0,%1,%2,%3},{%4,%5,%6,%7},{%8,%9},{%0,%1,%2,%3};"
        : "+f"(c[0]),"+f"(c[1]),"+f"(c[2]),"+f"(c[3])
        : "r"(a[0]),"r"(a[1]),"r"(a[2]),"r"(a[3]),"r"(b[0]),"r"(b[1]));
}
__device__ __forceinline__ unsigned cat2(__nv_bfloat16 a, __nv_bfloat16 b){
    unsigned short ua = *reinterpret_cast<unsigned short*>(&a);
    unsigned short ub = *reinterpret_cast<unsigned short*>(&b);
    return ((unsigned)ub << 16) | ua;
}

// SMEM tile layout (per buffer): A 64 rows x 32 bf16 (stride 40), B 32 k-rows x 128 n (stride 136)
#define OFF_AH 0
#define OFF_AL 5120
#define OFF_BH 10240
#define OFF_BL 18944
#define BUFB   28672

// shared mma core: 8 warps, warp owns M64 x N16 (4 m-tiles x 2 n-tiles), 2 k-steps
__device__ __forceinline__ void mma_block(float (&c)[4][2][4], unsigned base, int aoff, int boff){
    #pragma unroll
    for (int ks = 0; ks < 2; ks++){
        unsigned ah[4][4], al[4][4], bh[2][2], bl2[2][2];
        #pragma unroll
        for (int mt = 0; mt < 4; mt++){
            ldm_x4(ah[mt], base + OFF_AH + mt*1280 + aoff + ks*32);
            ldm_x4(al[mt], base + OFF_AL + mt*1280 + aoff + ks*32);
        }
        #pragma unroll
        for (int nt = 0; nt < 2; nt++){
            ldm_x2t(bh[nt],  base + OFF_BH + ks*4352 + boff + nt*16);
            ldm_x2t(bl2[nt], base + OFF_BL + ks*4352 + boff + nt*16);
        }
        #pragma unroll
        for (int mt = 0; mt < 4; mt++)
            #pragma unroll
            for (int nt = 0; nt < 2; nt++){
                mma_bf(c[mt][nt], ah[mt], bh[nt]);
                mma_bf(c[mt][nt], al[mt], bh[nt]);
                mma_bf(c[mt][nt], ah[mt], bl2[nt]);
            }
    }
}

// ---------------- K1: scatter multi-hot counts + zero accumulators ----------
__global__ void k1_scatter(const int* __restrict__ tags){
    int p = blockIdx.x*256 + threadIdx.x;       // 8192 threads
    if (blockIdx.x == 0 && threadIdx.x < 128) g_istat[threadIdx.x] = 0;
    for (int z = p; z < B*H4; z += 8192) g_accum[z] = 0.0f;
    int b = p >> 7;
    const int* t = tags + p*16;
    int v[16];
    #pragma unroll
    for (int i = 0; i < 16; i++) v[i] = t[i];
    #pragma unroll
    for (int i = 0; i < 16; i++){
        bool dup = false;
        #pragma unroll
        for (int s = 0; s < 16; s++) if (s < i) dup = dup || (v[s] == v[i]);
        if (!dup) atomicAdd(&g_counts[v[i]*B + b], 1.0f);
    }
}

// ---------------- K2: per-batch stats (integer-exact, deterministic) --------
__global__ void k2a_stats(){
    int tid = threadIdx.x;
    int b = tid & 63;
    int s = 0, sq = 0;
    for (int idx = blockIdx.x*256 + tid; idx < NT*B; idx += 160*256){
        int c = __float2int_rn(g_counts[idx]);
        s += c; sq += c*c;
    }
    atomicAdd(&g_istat[b], s);
    atomicAdd(&g_istat[64 + b], sq);
}

// ---------------- K3: write y (output #1); computes mu/rstd inline ----------
__global__ void __launch_bounds__(256) k3_y(const float* __restrict__ fc,
                                            const float* __restrict__ lng,
                                            const float* __restrict__ lnb,
                                            float* __restrict__ y){
    __shared__ float t[64*65];
    __shared__ float mu_s[64], rs_s[64];
    int tid = threadIdx.x;
    int j0 = blockIdx.x * 64;
    if (tid < 64){
        float mu  = (float)g_istat[tid] / (float)NT;
        float var = (float)g_istat[64 + tid] / (float)NT - mu*mu;
        mu_s[tid] = mu; rs_s[tid] = rsqrtf(var + 1e-5f);
    }
    #pragma unroll
    for (int i = 0; i < 16; i++){
        int idx = i*256 + tid; int r = idx >> 6, b = idx & 63; int j = j0 + r;
        t[r*65 + b] = (j < NT) ? g_counts[j*B + b] : 0.0f;
    }
    __syncthreads();
    #pragma unroll
    for (int i = 0; i < 16; i++){
        int idx = i*256 + tid; int b = idx >> 6, r = idx & 63; int j = j0 + r;
        if (j < NT)
            y[(size_t)b*NT1 + 1 + j] = (t[r*65 + b] - mu_s[b]) * rs_s[b] * lng[j] + lnb[j];
    }
    if (blockIdx.x == 0 && tid < B) y[(size_t)tid*NT1] = fc[tid] * 0.01f;
}

// ---------------- K4: GEMM1 y[64,20001] @ w1[20001,1024] via bf16-split mma --
// grid (8 n-blocks x 36 k-blocks); NB=128 cols, K-per-block 576 (18 chunks of 32)
#define KB4  36
#define KP4  576
#define NCH4 18
__global__ void __launch_bounds__(256) k4_mma(const float* __restrict__ y,
                                              const float* __restrict__ w1){
    extern __shared__ __align__(16) char sm4[];
    int tid = threadIdx.x, lane = tid & 31, wid = tid >> 5;
    int cbase = blockIdx.x * 128;
    int k00 = blockIdx.y * KP4;
    unsigned smb = (unsigned)__cvta_generic_to_shared(sm4);

    float c[4][2][4];
    #pragma unroll
    for (int mt = 0; mt < 4; mt++)
        #pragma unroll
        for (int nt = 0; nt < 2; nt++)
            #pragma unroll
            for (int q = 0; q < 4; q++) c[mt][nt][q] = 0.0f;

    const int aoff = (lane & 15)*80 + (lane >> 4)*16;
    const int boff = (lane & 15)*272 + wid*32;

    float4 wreg[4]; float areg[8];

    auto LOADS = [&](int k0){
        #pragma unroll
        for (int i = 0; i < 4; i++){
            int idx = i*256 + tid; int r = idx >> 5, c4 = idx & 31;
            int k = k0 + r;
            wreg[i] = (k < NT1)
                ? *reinterpret_cast<const float4*>(w1 + (size_t)k*1024 + cbase + c4*4)
                : make_float4(0.f,0.f,0.f,0.f);
        }
        #pragma unroll
        for (int i = 0; i < 8; i++){
            int idx = i*256 + tid; int b = idx >> 5, cc = idx & 31;
            int k = k0 + cc;
            areg[i] = (k < NT1) ? y[(size_t)b*NT1 + k] : 0.f;
        }
    };
    auto STORES = [&](char* buf){
        #pragma unroll
        for (int i = 0; i < 4; i++){
            int idx = i*256 + tid; int r = idx >> 5, c4 = idx & 31;
            float4 v = wreg[i];
            __nv_bfloat16 h0 = __float2bfloat16(v.x), h1 = __float2bfloat16(v.y);
            __nv_bfloat16 h2 = __float2bfloat16(v.z), h3 = __float2bfloat16(v.w);
            __nv_bfloat16 l0 = __float2bfloat16(v.x - __bfloat162float(h0));
            __nv_bfloat16 l1 = __float2bfloat16(v.y - __bfloat162float(h1));
            __nv_bfloat16 l2 = __float2bfloat16(v.z - __bfloat162float(h2));
            __nv_bfloat16 l3 = __float2bfloat16(v.w - __bfloat162float(h3));
            *reinterpret_cast<uint2*>(buf + OFF_BH + r*272 + c4*8) = make_uint2(cat2(h0,h1), cat2(h2,h3));
            *reinterpret_cast<uint2*>(buf + OFF_BL + r*272 + c4*8) = make_uint2(cat2(l0,l1), cat2(l2,l3));
        }
        #pragma unroll
        for (int i = 0; i < 8; i++){
            int idx = i*256 + tid; int b = idx >> 5, cc = idx & 31;
            __nv_bfloat16 h = __float2bfloat16(areg[i]);
            *reinterpret_cast<__nv_bfloat16*>(buf + OFF_AH + b*80 + cc*2) = h;
            *reinterpret_cast<__nv_bfloat16*>(buf + OFF_AL + b*80 + cc*2) =
                __float2bfloat16(areg[i] - __bfloat162float(h));
        }
    };

    LOADS(k00); STORES(sm4); __syncthreads();
    for (int ch = 0; ch < NCH4; ch++){
        unsigned curoff = (unsigned)(ch & 1) * BUFB;
        if (ch + 1 < NCH4) LOADS(k00 + (ch + 1)*32);
        mma_block(c, smb + curoff, aoff, boff);
        if (ch + 1 < NCH4) STORES(sm4 + (BUFB - curoff));
        __syncthreads();
    }

    #pragma unroll
    for (int mt = 0; mt < 4; mt++)
        #pragma unroll
        for (int nt = 0; nt < 2; nt++){
            int r0 = mt*16 + (lane >> 2);
            int col = cbase + wid*16 + nt*8 + (lane & 3)*2;
            atomicAdd(&g_accum[r0*1024 + col],       c[mt][nt][0]);
            atomicAdd(&g_accum[r0*1024 + col + 1],   c[mt][nt][1]);
            atomicAdd(&g_accum[(r0+8)*1024 + col],     c[mt][nt][2]);
            atomicAdd(&g_accum[(r0+8)*1024 + col + 1], c[mt][nt][3]);
        }
}

// ---------------- K5 fused: finalize + gelu + LayerNorm -> h2 ---------------
__global__ void __launch_bounds__(256) k5_fused(const float* __restrict__ b1,
                                                const float* __restrict__ g2,
                                                const float* __restrict__ b2){
    __shared__ float r1[256], r2[256];
    int b = blockIdx.x, tid = threadIdx.x;
    float h[4]; float s_sum = 0.0f, s_sq = 0.0f;
    #pragma unroll
    for (int i = 0; i < 4; i++){
        int k = i*256 + tid;
        h[i] = gelu_exact(g_accum[b*1024 + k] + b1[k]);
        s_sum += h[i]; s_sq += h[i]*h[i];
    }
    r1[tid] = s_sum; r2[tid] = s_sq; __syncthreads();
    for (int o = 128; o > 0; o >>= 1){
        if (tid < o){ r1[tid] += r1[tid+o]; r2[tid] += r2[tid+o]; }
        __syncthreads();
    }
    float mu = r1[0] * (1.0f/1024.0f);
    float var = r2[0] * (1.0f/1024.0f) - mu*mu;
    float rs = rsqrtf(var + 1e-5f);
    #pragma unroll
    for (int i = 0; i < 4; i++){
        int k = i*256 + tid;
        g_h2[b*1024 + k] = (h[i] - mu)*rs*g2[k] + b2[k];
    }
}

// ---------------- small GEMM: split-K partial + reduce ----------------------
template<int K, int N, int KPER>
__global__ void __launch_bounds__(256) sg_part(const float* __restrict__ A,
                                               const float* __restrict__ W,
                                               float* __restrict__ P){
    __shared__ float a_s[64*32];
    __shared__ float w_s[32*64];
    int tid = threadIdx.x, lane = tid & 31, wid = tid >> 5;
    int cbase = blockIdx.x*64, kbase = blockIdx.y*KPER;
    float acc[8][2] = {};
    for (int kc = kbase; kc < kbase + KPER; kc += 32){
        #pragma unroll
        for (int i = 0; i < 8; i++){
            int idx = i*256 + tid; int b = idx >> 5, kk = idx & 31;
            a_s[b*32 + kk] = A[b*K + kc + kk];
        }
        #pragma unroll
        for (int i = 0; i < 8; i++){
            int idx = i*256 + tid; int kk = idx >> 6, c = idx & 63;
            w_s[kk*64 + c] = W[(size_t)(kc + kk)*N + cbase + c];
        }
        __syncthreads();
        #pragma unroll
        for (int kk = 0; kk < 32; kk++){
            float av[8], wv0, wv1;
            #pragma unroll
            for (int i = 0; i < 8; i++) av[i] = a_s[(wid*8 + i)*32 + kk];
            wv0 = w_s[kk*64 + lane]; wv1 = w_s[kk*64 + lane + 32];
            #pragma unroll
            for (int i = 0; i < 8; i++){
                acc[i][0] += av[i]*wv0;
                acc[i][1] += av[i]*wv1;
            }
        }
        __syncthreads();
    }
    #pragma unroll
    for (int i = 0; i < 8; i++){
        P[blockIdx.y*(64*N) + (wid*8 + i)*N + cbase + lane]      = acc[i][0];
        P[blockIdx.y*(64*N) + (wid*8 + i)*N + cbase + lane + 32] = acc[i][1];
    }
}

template<int S, int N, bool ACT>
__global__ void sg_reduce(const float* __restrict__ P, const float* __restrict__ bias,
                          float* __restrict__ out, float* __restrict__ out2){
    int i = blockIdx.x*256 + threadIdx.x;
    if (i >= 64*N) return;
    float s = bias[i % N];
    #pragma unroll
    for (int p = 0; p < S; p++) s += P[p*64*N + i];
    if (ACT) s = gelu_exact(s);
    out[i] = s;
    if (out2) out2[i] = s;
}

// reduce + gelu + bf16-split for the decoder input dd
__global__ void sg_reduce_dd(const float* __restrict__ P, const float* __restrict__ bias){
    int i = blockIdx.x*256 + threadIdx.x;
    if (i >= 64*1024) return;
    float s = bias[i & 1023];
    #pragma unroll
    for (int p = 0; p < 8; p++) s += P[p*64*1024 + i];
    s = gelu_exact(s);
    __nv_bfloat16 h = __float2bfloat16(s);
    g_ddh[i] = h;
    g_ddl[i] = __float2bfloat16(s - __bfloat162float(h));
}

// ---------------- K10: decoder GEMM dd[64,1024] @ wd2[1024,20001] -----------
// grid (157): NB=128 cols per CTA, full K=1024 (32 chunks), direct store + bias
__global__ void __launch_bounds__(256) k10_mma(const float* __restrict__ wd2,
                                               const float* __restrict__ bd2,
                                               float* __restrict__ dec){
    extern __shared__ __align__(16) char sm4[];
    int tid = threadIdx.x, lane = tid & 31, wid = tid >> 5;
    int cbase = blockIdx.x * 128;
    unsigned smb = (unsigned)__cvta_generic_to_shared(sm4);

    float c[4][2][4];
    #pragma unroll
    for (int mt = 0; mt < 4; mt++)
        #pragma unroll
        for (int nt = 0; nt < 2; nt++)
            #pragma unroll
            for (int q = 0; q < 4; q++) c[mt][nt][q] = 0.0f;

    const int aoff = (lane & 15)*80 + (lane >> 4)*16;
    const int boff = (lane & 15)*272 + wid*32;
    const int ab = tid >> 2, ac8 = (tid & 3)*8;

    uint4 ahreg, alreg; float wr[16];

    auto LOADS = [&](int k0){
        ahreg = *reinterpret_cast<const uint4*>(g_ddh + ab*1024 + k0 + ac8);
        alreg = *reinterpret_cast<const uint4*>(g_ddl + ab*1024 + k0 + ac8);
        #pragma unroll
        for (int i = 0; i < 8; i++){
            int idx = i*256 + tid; int r = idx >> 6, cp = idx & 63;
            int n0 = cbase + cp*2;
            const float* src = wd2 + (size_t)(k0 + r)*NT1 + n0;
            wr[2*i]   = (n0     < NT1) ? src[0] : 0.f;
            wr[2*i+1] = (n0 + 1 < NT1) ? src[1] : 0.f;
        }
    };
    auto STORES = [&](char* buf){
        *reinterpret_cast<uint4*>(buf + OFF_AH + ab*80 + ac8*2) = ahreg;
        *reinterpret_cast<uint4*>(buf + OFF_AL + ab*80 + ac8*2) = alreg;
        #pragma unroll
        for (int i = 0; i < 8; i++){
            int idx = i*256 + tid; int r = idx >> 6, cp = idx & 63;
            __nv_bfloat16 h0 = __float2bfloat16(wr[2*i]), h1 = __float2bfloat16(wr[2*i+1]);
            __nv_bfloat16 l0 = __float2bfloat16(wr[2*i]   - __bfloat162float(h0));
            __nv_bfloat16 l1 = __float2bfloat16(wr[2*i+1] - __bfloat162float(h1));
            *reinterpret_cast<unsigned*>(buf + OFF_BH + r*272 + cp*4) = cat2(h0, h1);
            *reinterpret_cast<unsigned*>(buf + OFF_BL + r*272 + cp*4) = cat2(l0, l1);
        }
    };

    LOADS(0); STORES(sm4); __syncthreads();
    for (int ch = 0; ch < 32; ch++){
        unsigned curoff = (unsigned)(ch & 1) * BUFB;
        if (ch + 1 < 32) LOADS((ch + 1)*32);
        mma_block(c, smb + curoff, aoff, boff);
        if (ch + 1 < 32) STORES(sm4 + (BUFB - curoff));
        __syncthreads();
    }

    #pragma unroll
    for (int mt = 0; mt < 4; mt++)
        #pragma unroll
        for (int nt = 0; nt < 2; nt++){
            int r0 = mt*16 + (lane >> 2);
            int n = cbase + wid*16 + nt*8 + (lane & 3)*2;
            if (n < NT1){
                float bv = __ldg(bd2 + n);
                dec[(size_t)r0*NT1 + n]     = c[mt][nt][0] + bv;
                dec[(size_t)(r0+8)*NT1 + n] = c[mt][nt][2] + bv;
            }
            if (n + 1 < NT1){
                float bv = __ldg(bd2 + n + 1);
                dec[(size_t)r0*NT1 + n + 1]     = c[mt][nt][1] + bv;
                dec[(size_t)(r0+8)*NT1 + n + 1] = c[mt][nt][3] + bv;
            }
        }
}

// ---------------- launch -----------------------------------------------------
extern "C" void kernel_launch(void* const* d_in, const int* in_sizes, int n_in,
                              void* d_out, int out_size){
    const int*   tags = (const int*)  d_in[0];
    const float* fc   = (const float*)d_in[1];
    const float* lng  = (const float*)d_in[2];
    const float* lnb  = (const float*)d_in[3];
    const float* w1   = (const float*)d_in[4];
    const float* b1   = (const float*)d_in[5];
    const float* ln2g = (const float*)d_in[6];
    const float* ln2b = (const float*)d_in[7];
    const float* we1  = (const float*)d_in[8];
    const float* be1  = (const float*)d_in[9];
    const float* we2  = (const float*)d_in[10];
    const float* be2  = (const float*)d_in[11];
    const float* wd1  = (const float*)d_in[12];
    const float* bd1  = (const float*)d_in[13];
    const float* wd2  = (const float*)d_in[14];
    const float* bd2  = (const float*)d_in[15];
    float* out = (float*)d_out;

    float *p_counts, *p_h2, *p_h3, *p_enc, *p_pbuf;
    cudaGetSymbolAddress((void**)&p_counts, g_counts);
    cudaGetSymbolAddress((void**)&p_h2,     g_h2);
    cudaGetSymbolAddress((void**)&p_h3,     g_h3);
    cudaGetSymbolAddress((void**)&p_enc,    g_encb);
    cudaGetSymbolAddress((void**)&p_pbuf,   g_pbuf);

    static int attr_set = 0;
    if (!attr_set){
        cudaFuncSetAttribute(k4_mma,  cudaFuncAttributeMaxDynamicSharedMemorySize, 2*BUFB);
        cudaFuncSetAttribute(k10_mma, cudaFuncAttributeMaxDynamicSharedMemorySize, 2*BUFB);
        attr_set = 1;
    }

    cudaMemsetAsync(p_counts, 0, (size_t)NT*B*sizeof(float));
    k1_scatter<<<32, 256>>>(tags);
    k2a_stats<<<160, 256>>>();
    k3_y<<<313, 256>>>(fc, lng, lnb, out);

    // GEMM1 on tensor cores (reads y from out)
    k4_mma<<<dim3(8, KB4), 256, 2*BUFB>>>(out, w1);
    k5_fused<<<64, 256>>>(b1, ln2g, ln2b);

    // h2 @ we1 (1024->1024) + gelu
    sg_part<1024, 1024, 32><<<dim3(16, 32), 256>>>(p_h2, we1, p_pbuf);
    sg_reduce<32, 1024, true><<<256, 256>>>(p_pbuf, be1, p_h3, (float*)0);
    // h3 @ we2 (1024->256) -> enc (output #2)
    sg_part<1024, 256, 32><<<dim3(4, 32), 256>>>(p_h3, we2, p_pbuf);
    sg_reduce<32, 256, false><<<64, 256>>>(p_pbuf, be2, out + ENC_OFF, p_enc);
    // enc @ wd1 (256->1024) + gelu -> dd (bf16 split)
    sg_part<256, 1024, 32><<<dim3(16, 8), 256>>>(p_enc, wd1, p_pbuf);
    sg_reduce_dd<<<256, 256>>>(p_pbuf, bd1);

    // decoder GEMM on tensor cores -> dec (output #3)
    k10_mma<<<157, 256, 2*BUFB>>>(wd2, bd2, out + DEC_OFF);
}

// round 12
// speedup vs baseline: 2.4403x; 1.0349x over previous
#include <cuda_runtime.h>
#include <cuda_bf16.h>
#include <math.h>

#define B   64
#define NT  20000
#define NT1 20001
#define H4  1024
#define HD  256
#define Y_SZ    (B*NT1)
#define ENC_OFF Y_SZ
#define DEC_OFF (Y_SZ + B*HD)

#define DP_STRIDE 20096      // 157*128, padded dec-partial row stride

// ---------------- scratch (device globals; no allocations) -----------------
__device__ float g_counts[NT*B];                 // [tag][batch]
__device__ int   g_istat[128];                   // [0:64) sum, [64:128) sumsq
__device__ float g_accum[B*H4];                  // GEMM1 split-K accumulator
__device__ float g_h2[B*H4], g_h3[B*H4], g_encb[B*HD];
__device__ __align__(16) __nv_bfloat16 g_ddh[B*H4], g_ddl[B*H4];
__device__ float g_pbuf[32*B*H4];                // small-GEMM split-K partials
__device__ float g_dpacc[2*B*DP_STRIDE];         // decoder split-K partials

__device__ __forceinline__ float gelu_exact(float x){
    return 0.5f * x * (1.0f + erff(x * 0.70710678118654752f));
}

// ---------------- mma.sync helpers (m16n8k16 bf16, row.col) ------------------
__device__ __forceinline__ void ldm_x4(unsigned r[4], unsigned addr){
    asm volatile("ldmatrix.sync.aligned.m8n8.x4.shared.b16 {%0,%1,%2,%3}, [%4];"
        : "=r"(r[0]),"=r"(r[1]),"=r"(r[2]),"=r"(r[3]) : "r"(addr));
}
__device__ __forceinline__ void ldm_x2t(unsigned r[2], unsigned addr){
    asm volatile("ldmatrix.sync.aligned.m8n8.x2.trans.shared.b16 {%0,%1}, [%2];"
        : "=r"(r[0]),"=r"(r[1]) : "r"(addr));
}
__device__ __forceinline__ void mma_bf(float c[4], const unsigned a[4], const unsigned b[2]){
    asm volatile("mma.sync.aligned.m16n8k16.row.col.f32.bf16.bf16.f32 "
        "{%0,%1,%2,%3},{%4,%5,%6,%7},{%8,%9},{%0,%1,%2,%3};"
        : "+f"(c[0]),"+f"(c[1]),"+f"(c[2]),"+f"(c[3])
        : "r"(a[0]),"r"(a[1]),"r"(a[2]),"r"(a[3]),"r"(b[0]),"r"(b[1]));
}
__device__ __forceinline__ unsigned cat2(__nv_bfloat16 a, __nv_bfloat16 b){
    unsigned short ua = *reinterpret_cast<unsigned short*>(&a);
    unsigned short ub = *reinterpret_cast<unsigned short*>(&b);
    return ((unsigned)ub << 16) | ua;
}

// SMEM tile layout (per buffer): A 64 rows x 32 bf16 (stride 40), B 32 k-rows x 128 n (stride 136)
#define OFF_AH 0
#define OFF_AL 5120
#define OFF_BH 10240
#define OFF_BL 18944
#define BUFB   28672

// shared mma core: 8 warps, warp owns M64 x N16 (4 m-tiles x 2 n-tiles), 2 k-steps
__device__ __forceinline__ void mma_block(float (&c)[4][2][4], unsigned base, int aoff, int boff){
    #pragma unroll
    for (int ks = 0; ks < 2; ks++){
        unsigned ah[4][4], al[4][4], bh[2][2], bl2[2][2];
        #pragma unroll
        for (int mt = 0; mt < 4; mt++){
            ldm_x4(ah[mt], base + OFF_AH + mt*1280 + aoff + ks*32);
            ldm_x4(al[mt], base + OFF_AL + mt*1280 + aoff + ks*32);
        }
        #pragma unroll
        for (int nt = 0; nt < 2; nt++){
            ldm_x2t(bh[nt],  base + OFF_BH + ks*4352 + boff + nt*16);
            ldm_x2t(bl2[nt], base + OFF_BL + ks*4352 + boff + nt*16);
        }
        #pragma unroll
        for (int mt = 0; mt < 4; mt++)
            #pragma unroll
            for (int nt = 0; nt < 2; nt++){
                mma_bf(c[mt][nt], ah[mt], bh[nt]);
                mma_bf(c[mt][nt], al[mt], bh[nt]);
                mma_bf(c[mt][nt], ah[mt], bl2[nt]);
            }
    }
}

// ---------------- K1: scatter multi-hot counts + zero accumulators ----------
__global__ void k1_scatter(const int* __restrict__ tags){
    int p = blockIdx.x*256 + threadIdx.x;       // 8192 threads
    if (blockIdx.x == 0 && threadIdx.x < 128) g_istat[threadIdx.x] = 0;
    for (int z = p; z < B*H4; z += 8192) g_accum[z] = 0.0f;
    int b = p >> 7;
    const int* t = tags + p*16;
    int v[16];
    #pragma unroll
    for (int i = 0; i < 16; i++) v[i] = t[i];
    #pragma unroll
    for (int i = 0; i < 16; i++){
        bool dup = false;
        #pragma unroll
        for (int s = 0; s < 16; s++) if (s < i) dup = dup || (v[s] == v[i]);
        if (!dup) atomicAdd(&g_counts[v[i]*B + b], 1.0f);
    }
}

// ---------------- K2: per-batch stats (integer-exact, deterministic) --------
__global__ void k2a_stats(){
    int tid = threadIdx.x;
    int b = tid & 63;
    int s = 0, sq = 0;
    for (int idx = blockIdx.x*256 + tid; idx < NT*B; idx += 160*256){
        int c = __float2int_rn(g_counts[idx]);
        s += c; sq += c*c;
    }
    atomicAdd(&g_istat[b], s);
    atomicAdd(&g_istat[64 + b], sq);
}

// ---------------- K3: write y (output #1); computes mu/rstd inline ----------
__global__ void __launch_bounds__(256) k3_y(const float* __restrict__ fc,
                                            const float* __restrict__ lng,
                                            const float* __restrict__ lnb,
                                            float* __restrict__ y){
    __shared__ float t[64*65];
    __shared__ float mu_s[64], rs_s[64];
    int tid = threadIdx.x;
    int j0 = blockIdx.x * 64;
    if (tid < 64){
        float mu  = (float)g_istat[tid] / (float)NT;
        float var = (float)g_istat[64 + tid] / (float)NT - mu*mu;
        mu_s[tid] = mu; rs_s[tid] = rsqrtf(var + 1e-5f);
    }
    #pragma unroll
    for (int i = 0; i < 16; i++){
        int idx = i*256 + tid; int r = idx >> 6, b = idx & 63; int j = j0 + r;
        t[r*65 + b] = (j < NT) ? g_counts[j*B + b] : 0.0f;
    }
    __syncthreads();
    #pragma unroll
    for (int i = 0; i < 16; i++){
        int idx = i*256 + tid; int b = idx >> 6, r = idx & 63; int j = j0 + r;
        if (j < NT)
            y[(size_t)b*NT1 + 1 + j] = (t[r*65 + b] - mu_s[b]) * rs_s[b] * lng[j] + lnb[j];
    }
    if (blockIdx.x == 0 && tid < B) y[(size_t)tid*NT1] = fc[tid] * 0.01f;
}

// ---------------- K4: GEMM1 y[64,20001] @ w1[20001,1024] via bf16-split mma --
// grid (8 n-blocks x 37 k-blocks) = 296 CTAs = exactly 2/SM.
#define KB4  37
#define KP4  544
#define NCH4 17
__global__ void __launch_bounds__(256) k4_mma(const float* __restrict__ y,
                                              const float* __restrict__ w1){
    extern __shared__ __align__(16) char sm4[];
    int tid = threadIdx.x, lane = tid & 31, wid = tid >> 5;
    int cbase = blockIdx.x * 128;
    int k00 = blockIdx.y * KP4;
    unsigned smb = (unsigned)__cvta_generic_to_shared(sm4);

    float c[4][2][4];
    #pragma unroll
    for (int mt = 0; mt < 4; mt++)
        #pragma unroll
        for (int nt = 0; nt < 2; nt++)
            #pragma unroll
            for (int q = 0; q < 4; q++) c[mt][nt][q] = 0.0f;

    const int aoff = (lane & 15)*80 + (lane >> 4)*16;
    const int boff = (lane & 15)*272 + wid*32;

    float4 wreg[4]; float areg[8];

    auto LOADS = [&](int k0){
        #pragma unroll
        for (int i = 0; i < 4; i++){
            int idx = i*256 + tid; int r = idx >> 5, c4 = idx & 31;
            int k = k0 + r;
            wreg[i] = (k < NT1)
                ? *reinterpret_cast<const float4*>(w1 + (size_t)k*1024 + cbase + c4*4)
                : make_float4(0.f,0.f,0.f,0.f);
        }
        #pragma unroll
        for (int i = 0; i < 8; i++){
            int idx = i*256 + tid; int b = idx >> 5, cc = idx & 31;
            int k = k0 + cc;
            areg[i] = (k < NT1) ? y[(size_t)b*NT1 + k] : 0.f;
        }
    };
    auto STORES = [&](char* buf){
        #pragma unroll
        for (int i = 0; i < 4; i++){
            int idx = i*256 + tid; int r = idx >> 5, c4 = idx & 31;
            float4 v = wreg[i];
            __nv_bfloat16 h0 = __float2bfloat16(v.x), h1 = __float2bfloat16(v.y);
            __nv_bfloat16 h2 = __float2bfloat16(v.z), h3 = __float2bfloat16(v.w);
            __nv_bfloat16 l0 = __float2bfloat16(v.x - __bfloat162float(h0));
            __nv_bfloat16 l1 = __float2bfloat16(v.y - __bfloat162float(h1));
            __nv_bfloat16 l2 = __float2bfloat16(v.z - __bfloat162float(h2));
            __nv_bfloat16 l3 = __float2bfloat16(v.w - __bfloat162float(h3));
            *reinterpret_cast<uint2*>(buf + OFF_BH + r*272 + c4*8) = make_uint2(cat2(h0,h1), cat2(h2,h3));
            *reinterpret_cast<uint2*>(buf + OFF_BL + r*272 + c4*8) = make_uint2(cat2(l0,l1), cat2(l2,l3));
        }
        #pragma unroll
        for (int i = 0; i < 8; i++){
            int idx = i*256 + tid; int b = idx >> 5, cc = idx & 31;
            __nv_bfloat16 h = __float2bfloat16(areg[i]);
            *reinterpret_cast<__nv_bfloat16*>(buf + OFF_AH + b*80 + cc*2) = h;
            *reinterpret_cast<__nv_bfloat16*>(buf + OFF_AL + b*80 + cc*2) =
                __float2bfloat16(areg[i] - __bfloat162float(h));
        }
    };

    LOADS(k00); STORES(sm4); __syncthreads();
    for (int ch = 0; ch < NCH4; ch++){
        unsigned curoff = (unsigned)(ch & 1) * BUFB;
        if (ch + 1 < NCH4) LOADS(k00 + (ch + 1)*32);
        mma_block(c, smb + curoff, aoff, boff);
        if (ch + 1 < NCH4) STORES(sm4 + (BUFB - curoff));
        __syncthreads();
    }

    #pragma unroll
    for (int mt = 0; mt < 4; mt++)
        #pragma unroll
        for (int nt = 0; nt < 2; nt++){
            int r0 = mt*16 + (lane >> 2);
            int col = cbase + wid*16 + nt*8 + (lane & 3)*2;
            atomicAdd(&g_accum[r0*1024 + col],       c[mt][nt][0]);
            atomicAdd(&g_accum[r0*1024 + col + 1],   c[mt][nt][1]);
            atomicAdd(&g_accum[(r0+8)*1024 + col],     c[mt][nt][2]);
            atomicAdd(&g_accum[(r0+8)*1024 + col + 1], c[mt][nt][3]);
        }
}

// ---------------- K5 fused: finalize + gelu + LayerNorm -> h2 ---------------
__global__ void __launch_bounds__(256) k5_fused(const float* __restrict__ b1,
                                                const float* __restrict__ g2,
                                                const float* __restrict__ b2){
    __shared__ float r1[256], r2[256];
    int b = blockIdx.x, tid = threadIdx.x;
    float h[4]; float s_sum = 0.0f, s_sq = 0.0f;
    #pragma unroll
    for (int i = 0; i < 4; i++){
        int k = i*256 + tid;
        h[i] = gelu_exact(g_accum[b*1024 + k] + b1[k]);
        s_sum += h[i]; s_sq += h[i]*h[i];
    }
    r1[tid] = s_sum; r2[tid] = s_sq; __syncthreads();
    for (int o = 128; o > 0; o >>= 1){
        if (tid < o){ r1[tid] += r1[tid+o]; r2[tid] += r2[tid+o]; }
        __syncthreads();
    }
    float mu = r1[0] * (1.0f/1024.0f);
    float var = r2[0] * (1.0f/1024.0f) - mu*mu;
    float rs = rsqrtf(var + 1e-5f);
    #pragma unroll
    for (int i = 0; i < 4; i++){
        int k = i*256 + tid;
        g_h2[b*1024 + k] = (h[i] - mu)*rs*g2[k] + b2[k];
    }
}

// ---------------- small GEMM: split-K partial + reduce ----------------------
template<int K, int N, int KPER>
__global__ void __launch_bounds__(256) sg_part(const float* __restrict__ A,
                                               const float* __restrict__ W,
                                               float* __restrict__ P){
    __shared__ float a_s[64*32];
    __shared__ float w_s[32*64];
    int tid = threadIdx.x, lane = tid & 31, wid = tid >> 5;
    int cbase = blockIdx.x*64, kbase = blockIdx.y*KPER;
    float acc[8][2] = {};
    for (int kc = kbase; kc < kbase + KPER; kc += 32){
        #pragma unroll
        for (int i = 0; i < 8; i++){
            int idx = i*256 + tid; int b = idx >> 5, kk = idx & 31;
            a_s[b*32 + kk] = A[b*K + kc + kk];
        }
        #pragma unroll
        for (int i = 0; i < 8; i++){
            int idx = i*256 + tid; int kk = idx >> 6, c = idx & 63;
            w_s[kk*64 + c] = W[(size_t)(kc + kk)*N + cbase + c];
        }
        __syncthreads();
        #pragma unroll
        for (int kk = 0; kk < 32; kk++){
            float av[8], wv0, wv1;
            #pragma unroll
            for (int i = 0; i < 8; i++) av[i] = a_s[(wid*8 + i)*32 + kk];
            wv0 = w_s[kk*64 + lane]; wv1 = w_s[kk*64 + lane + 32];
            #pragma unroll
            for (int i = 0; i < 8; i++){
                acc[i][0] += av[i]*wv0;
                acc[i][1] += av[i]*wv1;
            }
        }
        __syncthreads();
    }
    #pragma unroll
    for (int i = 0; i < 8; i++){
        P[blockIdx.y*(64*N) + (wid*8 + i)*N + cbase + lane]      = acc[i][0];
        P[blockIdx.y*(64*N) + (wid*8 + i)*N + cbase + lane + 32] = acc[i][1];
    }
}

template<int S, int N, bool ACT>
__global__ void sg_reduce(const float* __restrict__ P, const float* __restrict__ bias,
                          float* __restrict__ out, float* __restrict__ out2){
    int i = blockIdx.x*256 + threadIdx.x;
    if (i >= 64*N) return;
    float s = bias[i % N];
    #pragma unroll
    for (int p = 0; p < S; p++) s += P[p*64*N + i];
    if (ACT) s = gelu_exact(s);
    out[i] = s;
    if (out2) out2[i] = s;
}

// reduce + gelu + bf16-split for the decoder input dd
__global__ void sg_reduce_dd(const float* __restrict__ P, const float* __restrict__ bias){
    int i = blockIdx.x*256 + threadIdx.x;
    if (i >= 64*1024) return;
    float s = bias[i & 1023];
    #pragma unroll
    for (int p = 0; p < 8; p++) s += P[p*64*1024 + i];
    s = gelu_exact(s);
    __nv_bfloat16 h = __float2bfloat16(s);
    g_ddh[i] = h;
    g_ddl[i] = __float2bfloat16(s - __bfloat162float(h));
}

// ---------------- K10: decoder GEMM dd[64,1024] @ wd2[1024,20001] -----------
// grid (157 x 2 split-K): NB=128 cols, K=512 per split (16 chunks of 32)
__global__ void __launch_bounds__(256) k10_mma(const float* __restrict__ wd2,
                                               float* __restrict__ P){
    extern __shared__ __align__(16) char sm4[];
    int tid = threadIdx.x, lane = tid & 31, wid = tid >> 5;
    int cbase = blockIdx.x * 128;
    int kbase = blockIdx.y * 512;
    unsigned smb = (unsigned)__cvta_generic_to_shared(sm4);

    float c[4][2][4];
    #pragma unroll
    for (int mt = 0; mt < 4; mt++)
        #pragma unroll
        for (int nt = 0; nt < 2; nt++)
            #pragma unroll
            for (int q = 0; q < 4; q++) c[mt][nt][q] = 0.0f;

    const int aoff = (lane & 15)*80 + (lane >> 4)*16;
    const int boff = (lane & 15)*272 + wid*32;
    const int ab = tid >> 2, ac8 = (tid & 3)*8;

    uint4 ahreg, alreg; float wr[16];

    auto LOADS = [&](int k0){
        ahreg = *reinterpret_cast<const uint4*>(g_ddh + ab*1024 + k0 + ac8);
        alreg = *reinterpret_cast<const uint4*>(g_ddl + ab*1024 + k0 + ac8);
        #pragma unroll
        for (int i = 0; i < 8; i++){
            int idx = i*256 + tid; int r = idx >> 6, cp = idx & 63;
            int n0 = cbase + cp*2;
            const float* src = wd2 + (size_t)(k0 + r)*NT1 + n0;
            wr[2*i]   = (n0     < NT1) ? src[0] : 0.f;
            wr[2*i+1] = (n0 + 1 < NT1) ? src[1] : 0.f;
        }
    };
    auto STORES = [&](char* buf){
        *reinterpret_cast<uint4*>(buf + OFF_AH + ab*80 + ac8*2) = ahreg;
        *reinterpret_cast<uint4*>(buf + OFF_AL + ab*80 + ac8*2) = alreg;
        #pragma unroll
        for (int i = 0; i < 8; i++){
            int idx = i*256 + tid; int r = idx >> 6, cp = idx & 63;
            __nv_bfloat16 h0 = __float2bfloat16(wr[2*i]), h1 = __float2bfloat16(wr[2*i+1]);
            __nv_bfloat16 l0 = __float2bfloat16(wr[2*i]   - __bfloat162float(h0));
            __nv_bfloat16 l1 = __float2bfloat16(wr[2*i+1] - __bfloat162float(h1));
            *reinterpret_cast<unsigned*>(buf + OFF_BH + r*272 + cp*4) = cat2(h0, h1);
            *reinterpret_cast<unsigned*>(buf + OFF_BL + r*272 + cp*4) = cat2(l0, l1);
        }
    };

    LOADS(kbase); STORES(sm4); __syncthreads();
    for (int ch = 0; ch < 16; ch++){
        unsigned curoff = (unsigned)(ch & 1) * BUFB;
        if (ch + 1 < 16) LOADS(kbase + (ch + 1)*32);
        mma_block(c, smb + curoff, aoff, boff);
        if (ch + 1 < 16) STORES(sm4 + (BUFB - curoff));
        __syncthreads();
    }

    // store partials to padded-stride buffer (no guards needed: stride 20096)
    float* Pb = P + (size_t)blockIdx.y * (B*DP_STRIDE);
    #pragma unroll
    for (int mt = 0; mt < 4; mt++)
        #pragma unroll
        for (int nt = 0; nt < 2; nt++){
            int r0 = mt*16 + (lane >> 2);
            int n = cbase + wid*16 + nt*8 + (lane & 3)*2;
            *reinterpret_cast<float2*>(Pb + (size_t)r0*DP_STRIDE + n) =
                make_float2(c[mt][nt][0], c[mt][nt][1]);
            *reinterpret_cast<float2*>(Pb + (size_t)(r0+8)*DP_STRIDE + n) =
                make_float2(c[mt][nt][2], c[mt][nt][3]);
        }
}

__global__ void k10_reduce(const float* __restrict__ P, const float* __restrict__ bd2,
                           float* __restrict__ dec){
    int i = blockIdx.x*256 + threadIdx.x;
    if (i >= B*NT1) return;
    int b = i / NT1;
    int c = i - b*NT1;
    dec[i] = bd2[c] + P[(size_t)b*DP_STRIDE + c]
                    + P[(size_t)(B + b)*DP_STRIDE + c];
}

// ---------------- launch -----------------------------------------------------
extern "C" void kernel_launch(void* const* d_in, const int* in_sizes, int n_in,
                              void* d_out, int out_size){
    const int*   tags = (const int*)  d_in[0];
    const float* fc   = (const float*)d_in[1];
    const float* lng  = (const float*)d_in[2];
    const float* lnb  = (const float*)d_in[3];
    const float* w1   = (const float*)d_in[4];
    const float* b1   = (const float*)d_in[5];
    const float* ln2g = (const float*)d_in[6];
    const float* ln2b = (const float*)d_in[7];
    const float* we1  = (const float*)d_in[8];
    const float* be1  = (const float*)d_in[9];
    const float* we2  = (const float*)d_in[10];
    const float* be2  = (const float*)d_in[11];
    const float* wd1  = (const float*)d_in[12];
    const float* bd1  = (const float*)d_in[13];
    const float* wd2  = (const float*)d_in[14];
    const float* bd2  = (const float*)d_in[15];
    float* out = (float*)d_out;

    float *p_counts, *p_h2, *p_h3, *p_enc, *p_pbuf, *p_dpacc;
    cudaGetSymbolAddress((void**)&p_counts, g_counts);
    cudaGetSymbolAddress((void**)&p_h2,     g_h2);
    cudaGetSymbolAddress((void**)&p_h3,     g_h3);
    cudaGetSymbolAddress((void**)&p_enc,    g_encb);
    cudaGetSymbolAddress((void**)&p_pbuf,   g_pbuf);
    cudaGetSymbolAddress((void**)&p_dpacc,  g_dpacc);

    static int attr_set = 0;
    if (!attr_set){
        cudaFuncSetAttribute(k4_mma,  cudaFuncAttributeMaxDynamicSharedMemorySize, 2*BUFB);
        cudaFuncSetAttribute(k10_mma, cudaFuncAttributeMaxDynamicSharedMemorySize, 2*BUFB);
        attr_set = 1;
    }

    cudaMemsetAsync(p_counts, 0, (size_t)NT*B*sizeof(float));
    k1_scatter<<<32, 256>>>(tags);
    k2a_stats<<<160, 256>>>();
    k3_y<<<313, 256>>>(fc, lng, lnb, out);

    // GEMM1 on tensor cores (reads y from out)
    k4_mma<<<dim3(8, KB4), 256, 2*BUFB>>>(out, w1);
    k5_fused<<<64, 256>>>(b1, ln2g, ln2b);

    // h2 @ we1 (1024->1024) + gelu
    sg_part<1024, 1024, 32><<<dim3(16, 32), 256>>>(p_h2, we1, p_pbuf);
    sg_reduce<32, 1024, true><<<256, 256>>>(p_pbuf, be1, p_h3, (float*)0);
    // h3 @ we2 (1024->256) -> enc (output #2)
    sg_part<1024, 256, 32><<<dim3(4, 32), 256>>>(p_h3, we2, p_pbuf);
    sg_reduce<32, 256, false><<<64, 256>>>(p_pbuf, be2, out + ENC_OFF, p_enc);
    // enc @ wd1 (256->1024) + gelu -> dd (bf16 split)
    sg_part<256, 1024, 32><<<dim3(16, 8), 256>>>(p_enc, wd1, p_pbuf);
    sg_reduce_dd<<<256, 256>>>(p_pbuf, bd1);

    // decoder GEMM on tensor cores, split-K=2 -> partials -> dec (output #3)
    k10_mma<<<dim3(157, 2), 256, 2*BUFB>>>(wd2, p_dpacc);
    k10_reduce<<<5001, 256>>>(p_dpacc, bd2, out + DEC_OFF);
}